// round 4
// baseline (speedup 1.0000x reference)
#include <cuda_runtime.h>
#include <cstdint>
#include <math.h>

// ---------------- problem-scale device scratch (static, no allocation) ----------------
#define NMAX 40960
__device__ float4 g_p4[NMAX];      // x, y, z, |p|^2
__device__ int    g_anchors[8192];
__device__ double g_terms[8192];

#define KK 20
#define INFF __int_as_float(0x7f800000)
typedef unsigned long long ull;

// ---------------- prep: SoA float4 with precomputed |p|^2 ----------------
__global__ void prep_kernel(const float* __restrict__ pos, int N) {
    int j = blockIdx.x * blockDim.x + threadIdx.x;
    if (j < N) {
        float x = pos[3*j], y = pos[3*j+1], z = pos[3*j+2];
        float n2 = __fadd_rn(__fadd_rn(__fmul_rn(x,x), __fmul_rn(y,y)), __fmul_rn(z,z));
        g_p4[j] = make_float4(x, y, z, n2);
    }
}

// ---------------- FPS: 8-CTA cluster, flat warp-level exchange, no intra-loop syncs ----
#define FCT  8
#define FTPB 512
#define FTOT (FCT*FTPB)   // 4096 threads
#define FP   10           // ceil(40000/4096)
#define NPAIR (FP/2)
#define SLOTS 128         // 8 CTAs * 16 warps

__device__ __forceinline__ unsigned fps_mapa(unsigned addr, unsigned rank) {
    unsigned r;
    asm("mapa.shared::cluster.u32 %0, %1, %2;" : "=r"(r) : "r"(addr), "r"(rank));
    return r;
}
__device__ __forceinline__ unsigned smem_u32_(const void* p) {
    return (unsigned)__cvta_generic_to_shared(p);
}
__device__ __forceinline__ void cluster_sync_() {
    asm volatile("barrier.cluster.arrive.aligned;\n\tbarrier.cluster.wait.aligned;" ::: "memory");
}
__device__ __forceinline__ ull pack2(float lo, float hi) {
    ull v; asm("mov.b64 %0, {%1, %2};" : "=l"(v) : "r"(__float_as_uint(lo)), "r"(__float_as_uint(hi)));
    return v;
}
__device__ __forceinline__ void unpack2(ull v, float &lo, float &hi) {
    unsigned a, b; asm("mov.b64 {%0, %1}, %2;" : "=r"(a), "=r"(b) : "l"(v));
    lo = __uint_as_float(a); hi = __uint_as_float(b);
}
__device__ __forceinline__ ull add2_(ull a, ull b) {
    ull d; asm("add.rn.f32x2 %0, %1, %2;" : "=l"(d) : "l"(a), "l"(b)); return d;
}
__device__ __forceinline__ ull mul2_(ull a, ull b) {
    ull d; asm("mul.rn.f32x2 %0, %1, %2;" : "=l"(d) : "l"(a), "l"(b)); return d;
}
__device__ __forceinline__ ull fma2_(ull a, ull b, ull c) {
    ull d; asm("fma.rn.f32x2 %0, %1, %2, %3;" : "=l"(d) : "l"(a), "l"(b), "l"(c)); return d;
}

__global__ void __cluster_dims__(FCT,1,1) __launch_bounds__(FTPB,1)
fps_kernel(int N, int nA) {
    extern __shared__ float4 s_pts[];          // [FTPB*FP] point mirror for winner lookup
    __shared__ ull   s_key[2][SLOTS];          // tagged keys: val32 | encIdx16 | tag16
    __shared__ ull   s_xy [2][SLOTS];          // winner x,y
    __shared__ float s_z  [2][SLOTS];          // winner z

    int tid  = threadIdx.x;
    unsigned rank; asm("mov.u32 %0, %%cluster_ctarank;" : "=r"(rank));
    int gt   = (int)rank * FTPB + tid;
    int lane = tid & 31, wid = tid >> 5;
    int slot = (int)rank * 16 + wid;           // this warp's global slot

    // zero key tags (both buffers)
    if (tid < 2*SLOTS) ((ull*)s_key)[tid] = 0ull;

    // precompute remote addresses for this warp's slot (lanes 0..7 -> target rank = lane)
    unsigned ka0=0, ka1=0, xa0=0, xa1=0, za0=0, za1=0;
    if (lane < FCT) {
        ka0 = fps_mapa(smem_u32_(&s_key[0][slot]), (unsigned)lane);
        ka1 = fps_mapa(smem_u32_(&s_key[1][slot]), (unsigned)lane);
        xa0 = fps_mapa(smem_u32_(&s_xy [0][slot]), (unsigned)lane);
        xa1 = fps_mapa(smem_u32_(&s_xy [1][slot]), (unsigned)lane);
        za0 = fps_mapa(smem_u32_(&s_z  [0][slot]), (unsigned)lane);
        za1 = fps_mapa(smem_u32_(&s_z  [1][slot]), (unsigned)lane);
    }

    // register-resident points (packed pairs) + min-distance array
    ull X2[NPAIR], Y2[NPAIR], Z2[NPAIR];
    float md[FP];
    bool has10 = (9*FTOT + gt) < N;

    float4 a0 = g_p4[0];
    float bv = -1.0f; int bi = 0;
    float xs[FP], ys[FP], zs[FP];
    #pragma unroll
    for (int s = 0; s < FP; s++) {
        int gi = s*FTOT + gt;                  // < NMAX; pad reads zero-init tail
        float4 q = g_p4[gi];
        s_pts[tid*FP + s] = q;
        xs[s]=q.x; ys[s]=q.y; zs[s]=q.z;
        float dx=q.x-a0.x, dy=q.y-a0.y, dz=q.z-a0.z;
        float d = fmaf(dx,dx, fmaf(dy,dy, dz*dz));
        bool valid = (s < 9) || has10;
        md[s] = valid ? d : -1.0f;
        if (valid && d > bv) { bv = d; bi = gi; }
    }
    #pragma unroll
    for (int p = 0; p < NPAIR; p++) {
        X2[p] = pack2(xs[2*p], xs[2*p+1]);
        Y2[p] = pack2(ys[2*p], ys[2*p+1]);
        Z2[p] = pack2(zs[2*p], zs[2*p+1]);
    }
    if (rank == 0 && tid == 0) g_anchors[0] = 0;
    __syncthreads();      // s_pts + zeroed tags (CTA-local)
    cluster_sync_();      // visible cluster-wide before any remote store

    unsigned kbase0 = smem_u32_(&s_key[0][0]) + (unsigned)lane * 32;   // 4 slots/lane
    unsigned kbase1 = smem_u32_(&s_key[1][0]) + (unsigned)lane * 32;

    for (int it = 1; it < nA; ++it) {
        int buf = it & 1;
        unsigned tag = (unsigned)it & 0xFFFFu;

        // ---- warp argmax: (max value, min index on tie) ----
        unsigned vb   = __float_as_uint(bv);                  // bv >= 0 -> monotone bits
        unsigned wmax = __reduce_max_sync(0xFFFFFFFFu, vb);
        unsigned cand = (vb == wmax) ? (unsigned)bi : 0xFFFFFFFFu;
        unsigned widx = __reduce_min_sync(0xFFFFFFFFu, cand); // warp winner global idx

        // all lanes: broadcast winner pos from point mirror (same addr -> LDS broadcast)
        int tloc = (int)(widx & (FTOT-1)) - (int)rank * FTPB; // == wid*32 + winner lane
        int sI   = (int)(widx >> 12);
        float4 wp = s_pts[tloc*FP + sI];

        // lanes 0..7 push (pos, key) to all 8 CTAs; release orders pos before key
        if (lane < FCT) {
            unsigned ka = buf ? ka1 : ka0;
            unsigned xa = buf ? xa1 : xa0;
            unsigned za = buf ? za1 : za0;
            ull key = ((ull)wmax << 32) | ((ull)(0xFFFFu - widx) << 16) | (ull)tag;
            ull xy  = pack2(wp.x, wp.y);
            asm volatile("st.shared::cluster.u64 [%0], %1;" :: "r"(xa), "l"(xy) : "memory");
            asm volatile("st.shared::cluster.u32 [%0], %1;" :: "r"(za), "r"(__float_as_uint(wp.z)) : "memory");
            asm volatile("st.release.cluster.shared::cluster.u64 [%0], %1;" :: "r"(ka), "l"(key) : "memory");
        }

        // ---- poll own copy of all 128 keys (4 per lane), tag-checked ----
        unsigned kb = buf ? kbase1 : kbase0;
        ull kk[4];
        #pragma unroll
        for (int q = 0; q < 4; q++) {
            ull v;
            do {
                asm volatile("ld.volatile.shared.u64 %0, [%1];" : "=l"(v) : "r"(kb + (unsigned)(q*8)));
            } while ((unsigned)(v & 0xFFFFull) != tag);
            kk[q] = v;
        }

        // ---- local max over 4 (value desc, index asc via enc), then warp REDUX ----
        ull c0 = kk[0] >> 16, c1 = kk[1] >> 16, c2 = kk[2] >> 16, c3 = kk[3] >> 16;
        ull m01 = (c1 > c0) ? c1 : c0;
        ull m23 = (c3 > c2) ? c3 : c2;
        ull mlo = (m23 > m01) ? m23 : m01;
        unsigned val  = (unsigned)(mlo >> 16);
        unsigned encp = (unsigned)(mlo & 0xFFFFull);
        unsigned wv = __reduce_max_sync(0xFFFFFFFFu, val);
        unsigned ce = (val == wv) ? encp : 0u;
        unsigned we = __reduce_max_sync(0xFFFFFFFFu, ce);    // max enc == min idx
        int gidx = (int)(0xFFFFu - we);                       // global winner index
        int slotwin = (gidx >> 5) & (SLOTS - 1);              // owning warp slot

        // winner position (volatile local LDS; written before key by release order)
        ull xyv; unsigned zv;
        {
            unsigned xa = smem_u32_(&s_xy[buf][slotwin]);
            unsigned za = smem_u32_(&s_z [buf][slotwin]);
            asm volatile("ld.volatile.shared.u64 %0, [%1];" : "=l"(xyv) : "r"(xa));
            asm volatile("ld.volatile.shared.u32 %0, [%1];" : "=r"(zv)  : "r"(za));
        }
        float apx, apy; unpack2(xyv, apx, apy);
        float apz = __uint_as_float(zv);

        if (rank == 0 && tid == 0) g_anchors[it] = gidx;

        // ---- update min-distances (f32x2 packed) + local argmax ----
        ull nax = pack2(-apx, -apx), nay = pack2(-apy, -apy), naz = pack2(-apz, -apz);
        #pragma unroll
        for (int p = 0; p < NPAIR; p++) {
            ull dx2 = add2_(X2[p], nax);
            ull dy2 = add2_(Y2[p], nay);
            ull dz2 = add2_(Z2[p], naz);
            ull dd  = fma2_(dx2, dx2, fma2_(dy2, dy2, mul2_(dz2, dz2)));
            float dlo, dhi; unpack2(dd, dlo, dhi);
            md[2*p]   = fminf(md[2*p],   dlo);
            md[2*p+1] = fminf(md[2*p+1], dhi);
        }
        bv = md[0]; bi = gt;
        #pragma unroll
        for (int s = 1; s < 9; s++) {
            if (md[s] > bv) { bv = md[s]; bi = gt + s*FTOT; }
        }
        if (has10 && md[9] > bv) { bv = md[9]; bi = gt + 9*FTOT; }
    }
    cluster_sync_();
}

// ---------------- KNN + PCA + per-anchor loss term: one warp per anchor ----------------
__device__ __forceinline__ double wsum_d(double v) {
    #pragma unroll
    for (int o = 16; o > 0; o >>= 1) v += __shfl_xor_sync(0xFFFFFFFFu, v, o);
    return v;
}

__global__ void knn_loss_kernel(const float* __restrict__ vec_pred, int N, int nA) {
    int wid  = threadIdx.x >> 5;
    int lane = threadIdx.x & 31;
    int i = blockIdx.x * (blockDim.x >> 5) + wid;
    if (i >= nA) return;

    int a = g_anchors[i];
    float4 ap = g_p4[a];
    float na2 = ap.w;

    float vv[KK]; int ii[KK];
    #pragma unroll
    for (int k = 0; k < KK; k++) { vv[k] = INFF; ii[k] = 0x7fffffff; }

    int steps = N >> 5;
    #pragma unroll 4
    for (int s = 0; s < steps; s++) {
        int j = (s << 5) + lane;
        float4 q = g_p4[j];
        float dot = fmaf(ap.z, q.z, fmaf(ap.y, q.y, ap.x*q.x));
        float d2 = (na2 - 2.0f*dot) + q.w;               // reference's expansion
        if (d2 < vv[KK-1]) {
            float cd = d2; int cj = j;
            #pragma unroll
            for (int k = 0; k < KK; k++) {
                if (cd < vv[k]) { float tv=vv[k]; int ti=ii[k]; vv[k]=cd; ii[k]=cj; cd=tv; cj=ti; }
            }
        }
    }
    int rem = N - (steps << 5);
    if (rem > 0 && lane < rem) {
        int j = (steps << 5) + lane;
        float4 q = g_p4[j];
        float dot = fmaf(ap.z, q.z, fmaf(ap.y, q.y, ap.x*q.x));
        float d2 = (na2 - 2.0f*dot) + q.w;
        if (d2 < vv[KK-1]) {
            float cd = d2; int cj = j;
            #pragma unroll
            for (int k = 0; k < KK; k++) {
                if (cd < vv[k]) { float tv=vv[k]; int ti=ii[k]; vv[k]=cd; ii[k]=cj; cd=tv; cj=ti; }
            }
        }
    }

    // 20-round warp merge; ties -> lower index (matches jax top_k)
    int nbr = -1;
    for (int r = 0; r < KK; r++) {
        unsigned m = __float_as_uint(vv[0]);
        m = (m & 0x80000000u) ? ~m : (m | 0x80000000u);
        ull key = ((ull)m << 32) | (unsigned)ii[0];
        #pragma unroll
        for (int o = 16; o > 0; o >>= 1) {
            ull k2 = __shfl_xor_sync(0xFFFFFFFFu, key, o);
            if (k2 < key) key = k2;
        }
        int widx = (int)(unsigned)key;
        if (lane == r) nbr = widx;
        if (ii[0] == widx) {
            #pragma unroll
            for (int k = 0; k < KK-1; k++) { vv[k]=vv[k+1]; ii[k]=ii[k+1]; }
            vv[KK-1] = INFF; ii[KK-1] = 0x7fffffff;
        }
    }

    // gather neighbors (lanes 0..19), covariance in double
    double x=0.0, y=0.0, z=0.0;
    if (lane < KK) { float4 q = g_p4[nbr]; x=q.x; y=q.y; z=q.z; }
    double sx = wsum_d(x), sy = wsum_d(y), sz = wsum_d(z);
    double mx = sx/KK, my = sy/KK, mz = sz/KK;
    double cx = (lane<KK) ? x-mx : 0.0;
    double cy = (lane<KK) ? y-my : 0.0;
    double cz = (lane<KK) ? z-mz : 0.0;
    double xx = wsum_d(cx*cx), xy = wsum_d(cx*cy), xz = wsum_d(cx*cz);
    double yy = wsum_d(cy*cy), yz = wsum_d(cy*cz), zz = wsum_d(cz*cz);

    if (lane == 0) {
        double A=xx, B=yy, C=zz, D=xy, E=xz, F=yz;
        double p1 = D*D + E*E + F*F;
        double q3 = (A+B+C)/3.0;
        double p2 = (A-q3)*(A-q3) + (B-q3)*(B-q3) + (C-q3)*(C-q3) + 2.0*p1;
        double p  = sqrt(p2/6.0);
        double lam;
        if (p > 0.0) {
            double ip = 1.0/p;
            double b00=(A-q3)*ip, b11=(B-q3)*ip, b22=(C-q3)*ip;
            double b01=D*ip, b02=E*ip, b12=F*ip;
            double det = b00*(b11*b22 - b12*b12)
                       - b01*(b01*b22 - b12*b02)
                       + b02*(b01*b12 - b11*b02);
            double rr = det*0.5;
            rr = fmin(1.0, fmax(-1.0, rr));
            lam = q3 + 2.0*p*cos(acos(rr)/3.0);
        } else lam = q3;

        double r0x=A-lam, r0y=D,     r0z=E;
        double r1x=D,     r1y=B-lam, r1z=F;
        double r2x=E,     r2y=F,     r2z=C-lam;
        double c1x=r0y*r1z-r0z*r1y, c1y=r0z*r1x-r0x*r1z, c1z=r0x*r1y-r0y*r1x;
        double c2x=r0y*r2z-r0z*r2y, c2y=r0z*r2x-r0x*r2z, c2z=r0x*r2y-r0y*r2x;
        double c3x=r1y*r2z-r1z*r2y, c3y=r1z*r2x-r1x*r2z, c3z=r1x*r2y-r1y*r2x;
        double n1=c1x*c1x+c1y*c1y+c1z*c1z;
        double n2=c2x*c2x+c2y*c2y+c2z*c2z;
        double n3=c3x*c3x+c3y*c3y+c3z*c3z;
        double vx=c1x, vy=c1y, vz=c1z, bn=n1;
        if (n2 > bn) { vx=c2x; vy=c2y; vz=c2z; bn=n2; }
        if (n3 > bn) { vx=c3x; vy=c3y; vz=c3z; bn=n3; }
        if (bn < 1e-300) { vx=1.0; vy=0.0; vz=0.0; bn=1.0; }
        double inv = rsqrt(bn);
        vx*=inv; vy*=inv; vz*=inv;

        const float* vp = vec_pred + 3*i;
        double ax=vp[0], ay=vp[1], az=vp[2];
        double nrm = sqrt(ax*ax + ay*ay + az*az);
        if (nrm < 1e-8) nrm = 1e-8;
        double dt = ax*vx + ay*vy + az*vz;
        double ac = fabs(dt)/nrm;
        g_terms[i] = log(ac + 1e-6);
    }
}

// ---------------- final deterministic reduction ----------------
__global__ void reduce_kernel(int nA, float* __restrict__ out) {
    __shared__ double sm[32];
    int tid = threadIdx.x;
    double s = 0.0;
    for (int i = tid; i < nA; i += blockDim.x) s += g_terms[i];
    s = wsum_d(s);
    if ((tid & 31) == 0) sm[tid >> 5] = s;
    __syncthreads();
    if (tid < 32) {
        double v = (tid < (int)(blockDim.x >> 5)) ? sm[tid] : 0.0;
        v = wsum_d(v);
        if (tid == 0) out[0] = (float)(-v / (double)nA);
    }
}

// ---------------- launch ----------------
extern "C" void kernel_launch(void* const* d_in, const int* in_sizes, int n_in,
                              void* d_out, int out_size) {
    const float* vec_pred = (const float*)d_in[0];
    const float* pos      = (const float*)d_in[1];
    int N  = in_sizes[1] / 3;
    int nA = (int)ceil(0.1 * (double)N);

    int smem = FTPB * FP * (int)sizeof(float4);   // 80 KB point mirror
    cudaFuncSetAttribute(fps_kernel, cudaFuncAttributeMaxDynamicSharedMemorySize, smem);

    prep_kernel<<<(N + 255)/256, 256>>>(pos, N);
    fps_kernel<<<FCT, FTPB, smem>>>(N, nA);
    int wpb = 8;
    knn_loss_kernel<<<(nA + wpb - 1)/wpb, 32*wpb>>>(vec_pred, N, nA);
    reduce_kernel<<<1, 512>>>(nA, (float*)d_out);
}

// round 5
// speedup vs baseline: 1.3210x; 1.3210x over previous
#include <cuda_runtime.h>
#include <cstdint>
#include <math.h>

// ---------------- problem-scale device scratch (static, no allocation) ----------------
#define NMAX 40960
__device__ float4 g_p4[NMAX];      // x, y, z, |p|^2
__device__ int    g_anchors[8192];
__device__ double g_terms[8192];

#define KK 20
#define INFF __int_as_float(0x7f800000)
typedef unsigned long long ull;

// ---------------- prep: SoA float4 with precomputed |p|^2 ----------------
__global__ void prep_kernel(const float* __restrict__ pos, int N) {
    int j = blockIdx.x * blockDim.x + threadIdx.x;
    if (j < N) {
        float x = pos[3*j], y = pos[3*j+1], z = pos[3*j+2];
        float n2 = __fadd_rn(__fadd_rn(__fmul_rn(x,x), __fmul_rn(y,y)), __fmul_rn(z,z));
        g_p4[j] = make_float4(x, y, z, n2);
    }
}

// ---------------- FPS: 8-CTA cluster, tagged-slot exchange, zero intra-loop syncs ----
#define FCT  8
#define FTPB 512
#define NW   (FTPB/32)    // 16 warps
#define FTOT (FCT*FTPB)   // 4096 threads
#define FP   10           // ceil(40000/4096)
#define NPAIR (FP/2)

__device__ __forceinline__ unsigned fps_mapa(unsigned addr, unsigned rank) {
    unsigned r;
    asm("mapa.shared::cluster.u32 %0, %1, %2;" : "=r"(r) : "r"(addr), "r"(rank));
    return r;
}
__device__ __forceinline__ unsigned smem_u32_(const void* p) {
    return (unsigned)__cvta_generic_to_shared(p);
}
__device__ __forceinline__ void cluster_sync_() {
    asm volatile("barrier.cluster.arrive.aligned;\n\tbarrier.cluster.wait.aligned;" ::: "memory");
}
__device__ __forceinline__ ull pack2(float lo, float hi) {
    ull v; asm("mov.b64 %0, {%1, %2};" : "=l"(v) : "r"(__float_as_uint(lo)), "r"(__float_as_uint(hi)));
    return v;
}
__device__ __forceinline__ void unpack2(ull v, float &lo, float &hi) {
    unsigned a, b; asm("mov.b64 {%0, %1}, %2;" : "=r"(a), "=r"(b) : "l"(v));
    lo = __uint_as_float(a); hi = __uint_as_float(b);
}
__device__ __forceinline__ ull add2_(ull a, ull b) {
    ull d; asm("add.rn.f32x2 %0, %1, %2;" : "=l"(d) : "l"(a), "l"(b)); return d;
}
__device__ __forceinline__ ull mul2_(ull a, ull b) {
    ull d; asm("mul.rn.f32x2 %0, %1, %2;" : "=l"(d) : "l"(a), "l"(b)); return d;
}
__device__ __forceinline__ ull fma2_(ull a, ull b, ull c) {
    ull d; asm("fma.rn.f32x2 %0, %1, %2, %3;" : "=l"(d) : "l"(a), "l"(b), "l"(c)); return d;
}

__global__ void __cluster_dims__(FCT,1,1) __launch_bounds__(FTPB,1)
fps_kernel(int N, int nA) {
    extern __shared__ float4 s_pts[];          // [FTPB*FP] point mirror for winner lookup
    __shared__ ull   s_wkey[NW];               // per-warp tagged keys (val32|enc16|tag16)
    __shared__ ull   s_xkey[2][FCT];           // exchanged tagged keys (double buffered)
    __shared__ ull   s_xy  [2][FCT];           // exchanged winner x,y
    __shared__ float s_z   [2][FCT];           // exchanged winner z

    int tid  = threadIdx.x;
    unsigned rank; asm("mov.u32 %0, %%cluster_ctarank;" : "=r"(rank));
    int gt   = (int)rank * FTPB + tid;
    int lane = tid & 31, wid = tid >> 5;

    // zero tags
    if (tid < 2*FCT) ((ull*)s_xkey)[tid] = 0ull;
    if (tid < NW)    s_wkey[tid] = 0ull;

    // remote addresses (lanes 0..7 of warp0 target rank = lane)
    unsigned rka0=0, rka1=0, rxa0=0, rxa1=0, rza0=0, rza1=0;
    if (wid == 0 && lane < FCT) {
        rka0 = fps_mapa(smem_u32_(&s_xkey[0][rank]), (unsigned)lane);
        rka1 = fps_mapa(smem_u32_(&s_xkey[1][rank]), (unsigned)lane);
        rxa0 = fps_mapa(smem_u32_(&s_xy [0][rank]), (unsigned)lane);
        rxa1 = fps_mapa(smem_u32_(&s_xy [1][rank]), (unsigned)lane);
        rza0 = fps_mapa(smem_u32_(&s_z  [0][rank]), (unsigned)lane);
        rza1 = fps_mapa(smem_u32_(&s_z  [1][rank]), (unsigned)lane);
    }

    // register-resident points (packed pairs) + min-distance array
    ull X2[NPAIR], Y2[NPAIR], Z2[NPAIR];
    float md[FP];
    bool has10 = (9*FTOT + gt) < N;

    float4 a0 = g_p4[0];
    float bv = -1.0f; int bi = 0;
    float xs[FP], ys[FP], zs[FP];
    #pragma unroll
    for (int s = 0; s < FP; s++) {
        int gi = s*FTOT + gt;                  // < NMAX; pad reads zero-init tail
        float4 q = g_p4[gi];
        s_pts[tid*FP + s] = q;
        xs[s]=q.x; ys[s]=q.y; zs[s]=q.z;
        float dx=q.x-a0.x, dy=q.y-a0.y, dz=q.z-a0.z;
        float d = fmaf(dx,dx, fmaf(dy,dy, dz*dz));
        bool valid = (s < 9) || has10;
        md[s] = valid ? d : -1.0f;
        if (valid && d > bv) { bv = d; bi = gi; }
    }
    #pragma unroll
    for (int p = 0; p < NPAIR; p++) {
        X2[p] = pack2(xs[2*p], xs[2*p+1]);
        Y2[p] = pack2(ys[2*p], ys[2*p+1]);
        Z2[p] = pack2(zs[2*p], zs[2*p+1]);
    }
    if (rank == 0 && tid == 0) g_anchors[0] = 0;
    __syncthreads();      // s_pts + zeroed tags (CTA-local)
    cluster_sync_();      // visible cluster-wide before any remote store

    unsigned wkbase = smem_u32_(&s_wkey[0]);
    unsigned xk0 = smem_u32_(&s_xkey[0][0]);
    unsigned xk1 = smem_u32_(&s_xkey[1][0]);

    for (int it = 1; it < nA; ++it) {
        int buf = it & 1;
        ull tag = (ull)((unsigned)it & 0xFFFFu);

        // ---- warp argmax: (max value, min index on tie) ----
        unsigned vb   = __float_as_uint(bv);                  // bv >= 0 -> monotone bits
        unsigned wmax = __reduce_max_sync(0xFFFFFFFFu, vb);
        unsigned cand = (vb == wmax) ? (unsigned)bi : 0xFFFFFFFFu;
        unsigned widx = __reduce_min_sync(0xFFFFFFFFu, cand); // warp winner global idx

        // post warp key (single tagged word -> race-free without bar.sync)
        if (lane == 0) {
            ull wkey = ((ull)wmax << 32) | ((ull)(0xFFFFu - widx) << 16) | tag;
            asm volatile("st.volatile.shared.u64 [%0], %1;" :: "r"(wkbase + (unsigned)(wid*8)), "l"(wkey) : "memory");
        }

        // ---- warp0: combine 16 warp keys, ship block partial to 8 CTAs ----
        if (wid == 0) {
            ull k = 0ull;
            if (lane < NW) {
                unsigned a = wkbase + (unsigned)(lane*8);
                do {
                    asm volatile("ld.volatile.shared.u64 %0, [%1];" : "=l"(k) : "r"(a));
                } while ((unsigned)(k & 0xFFFFull) != (unsigned)tag);
            }
            unsigned kv   = (unsigned)(k >> 32);
            unsigned bmax = __reduce_max_sync(0xFFFFFFFFu, kv);
            unsigned cenc = (kv == bmax && lane < NW) ? (unsigned)((k >> 16) & 0xFFFFull) : 0u;
            unsigned benc = __reduce_max_sync(0xFFFFFFFFu, cenc);   // max enc == min idx
            // block winner belongs to this CTA: locate in point mirror
            unsigned bidx = 0xFFFFu - benc;
            int tloc = (int)(bidx & (FTOT-1)) - (int)rank * FTPB;
            int sI   = (int)(bidx >> 12);
            float4 bp = s_pts[tloc*FP + sI];
            if (lane < FCT) {
                ull blkkey = ((ull)bmax << 32) | ((ull)benc << 16) | tag;
                unsigned ka = buf ? rka1 : rka0;
                unsigned xa = buf ? rxa1 : rxa0;
                unsigned za = buf ? rza1 : rza0;
                ull xy = pack2(bp.x, bp.y);
                asm volatile("st.shared::cluster.u64 [%0], %1;" :: "r"(xa), "l"(xy) : "memory");
                asm volatile("st.shared::cluster.u32 [%0], %1;" :: "r"(za), "r"(__float_as_uint(bp.z)) : "memory");
                asm volatile("st.release.cluster.shared::cluster.u64 [%0], %1;" :: "r"(ka), "l"(blkkey) : "memory");
            }
        }

        // ---- all warps: poll the 8 exchanged keys (pipelined), combine ----
        unsigned kb = buf ? xk1 : xk0;
        ull kk[FCT];
        bool ok;
        do {
            #pragma unroll
            for (int r = 0; r < FCT; r++)
                asm volatile("ld.acquire.cluster.shared::cta.b64 %0, [%1];" : "=l"(kk[r]) : "r"(kb + (unsigned)(r*8)) : "memory");
            ok = true;
            #pragma unroll
            for (int r = 0; r < FCT; r++) ok &= ((unsigned)(kk[r] & 0xFFFFull) == (unsigned)tag);
        } while (!ok);

        ull ka_ = kk[0]; int ra = 0; if (kk[1] > ka_) { ka_ = kk[1]; ra = 1; }
        ull kb_ = kk[2]; int rb = 2; if (kk[3] > kb_) { kb_ = kk[3]; rb = 3; }
        ull kc_ = kk[4]; int rc = 4; if (kk[5] > kc_) { kc_ = kk[5]; rc = 5; }
        ull kd_ = kk[6]; int rd = 6; if (kk[7] > kd_) { kd_ = kk[7]; rd = 7; }
        if (kb_ > ka_) { ka_ = kb_; ra = rb; }
        if (kd_ > kc_) { kc_ = kd_; rc = rd; }
        if (kc_ > ka_) { ka_ = kc_; ra = rc; }

        // winner position (local copy; release/acquire on key orders these)
        ull xyv; unsigned zv;
        {
            unsigned xa = smem_u32_(&s_xy[buf][ra]);
            unsigned za = smem_u32_(&s_z [buf][ra]);
            asm volatile("ld.volatile.shared.u64 %0, [%1];" : "=l"(xyv) : "r"(xa));
            asm volatile("ld.volatile.shared.u32 %0, [%1];" : "=r"(zv)  : "r"(za));
        }
        float apx, apy; unpack2(xyv, apx, apy);
        float apz = __uint_as_float(zv);

        if (rank == 0 && tid == 0)
            g_anchors[it] = (int)(0xFFFFu - (unsigned)((ka_ >> 16) & 0xFFFFull));

        // ---- update min-distances (f32x2 packed) + local argmax ----
        ull nax = pack2(-apx, -apx), nay = pack2(-apy, -apy), naz = pack2(-apz, -apz);
        #pragma unroll
        for (int p = 0; p < NPAIR; p++) {
            ull dx2 = add2_(X2[p], nax);
            ull dy2 = add2_(Y2[p], nay);
            ull dz2 = add2_(Z2[p], naz);
            ull dd  = fma2_(dx2, dx2, fma2_(dy2, dy2, mul2_(dz2, dz2)));
            float dlo, dhi; unpack2(dd, dlo, dhi);
            md[2*p]   = fminf(md[2*p],   dlo);
            md[2*p+1] = fminf(md[2*p+1], dhi);
        }
        bv = md[0]; bi = gt;
        #pragma unroll
        for (int s = 1; s < 9; s++) {
            if (md[s] > bv) { bv = md[s]; bi = gt + s*FTOT; }
        }
        if (has10 && md[9] > bv) { bv = md[9]; bi = gt + 9*FTOT; }
    }
    cluster_sync_();
}

// ---------------- KNN + PCA + per-anchor loss term: one warp per anchor ----------------
__device__ __forceinline__ double wsum_d(double v) {
    #pragma unroll
    for (int o = 16; o > 0; o >>= 1) v += __shfl_xor_sync(0xFFFFFFFFu, v, o);
    return v;
}

__global__ void knn_loss_kernel(const float* __restrict__ vec_pred, int N, int nA) {
    int wid  = threadIdx.x >> 5;
    int lane = threadIdx.x & 31;
    int i = blockIdx.x * (blockDim.x >> 5) + wid;
    if (i >= nA) return;

    int a = g_anchors[i];
    float4 ap = g_p4[a];
    float na2 = ap.w;

    float vv[KK]; int ii[KK];
    #pragma unroll
    for (int k = 0; k < KK; k++) { vv[k] = INFF; ii[k] = 0x7fffffff; }

    int steps = N >> 5;
    #pragma unroll 4
    for (int s = 0; s < steps; s++) {
        int j = (s << 5) + lane;
        float4 q = g_p4[j];
        float dot = fmaf(ap.z, q.z, fmaf(ap.y, q.y, ap.x*q.x));
        float d2 = (na2 - 2.0f*dot) + q.w;               // reference's expansion
        if (d2 < vv[KK-1]) {
            float cd = d2; int cj = j;
            #pragma unroll
            for (int k = 0; k < KK; k++) {
                if (cd < vv[k]) { float tv=vv[k]; int ti=ii[k]; vv[k]=cd; ii[k]=cj; cd=tv; cj=ti; }
            }
        }
    }
    int rem = N - (steps << 5);
    if (rem > 0 && lane < rem) {
        int j = (steps << 5) + lane;
        float4 q = g_p4[j];
        float dot = fmaf(ap.z, q.z, fmaf(ap.y, q.y, ap.x*q.x));
        float d2 = (na2 - 2.0f*dot) + q.w;
        if (d2 < vv[KK-1]) {
            float cd = d2; int cj = j;
            #pragma unroll
            for (int k = 0; k < KK; k++) {
                if (cd < vv[k]) { float tv=vv[k]; int ti=ii[k]; vv[k]=cd; ii[k]=cj; cd=tv; cj=ti; }
            }
        }
    }

    // 20-round warp merge; ties -> lower index (matches jax top_k)
    int nbr = -1;
    for (int r = 0; r < KK; r++) {
        unsigned m = __float_as_uint(vv[0]);
        m = (m & 0x80000000u) ? ~m : (m | 0x80000000u);
        ull key = ((ull)m << 32) | (unsigned)ii[0];
        #pragma unroll
        for (int o = 16; o > 0; o >>= 1) {
            ull k2 = __shfl_xor_sync(0xFFFFFFFFu, key, o);
            if (k2 < key) key = k2;
        }
        int widx = (int)(unsigned)key;
        if (lane == r) nbr = widx;
        if (ii[0] == widx) {
            #pragma unroll
            for (int k = 0; k < KK-1; k++) { vv[k]=vv[k+1]; ii[k]=ii[k+1]; }
            vv[KK-1] = INFF; ii[KK-1] = 0x7fffffff;
        }
    }

    // gather neighbors (lanes 0..19), covariance in double
    double x=0.0, y=0.0, z=0.0;
    if (lane < KK) { float4 q = g_p4[nbr]; x=q.x; y=q.y; z=q.z; }
    double sx = wsum_d(x), sy = wsum_d(y), sz = wsum_d(z);
    double mx = sx/KK, my = sy/KK, mz = sz/KK;
    double cx = (lane<KK) ? x-mx : 0.0;
    double cy = (lane<KK) ? y-my : 0.0;
    double cz = (lane<KK) ? z-mz : 0.0;
    double xx = wsum_d(cx*cx), xy = wsum_d(cx*cy), xz = wsum_d(cx*cz);
    double yy = wsum_d(cy*cy), yz = wsum_d(cy*cz), zz = wsum_d(cz*cz);

    if (lane == 0) {
        double A=xx, B=yy, C=zz, D=xy, E=xz, F=yz;
        double p1 = D*D + E*E + F*F;
        double q3 = (A+B+C)/3.0;
        double p2 = (A-q3)*(A-q3) + (B-q3)*(B-q3) + (C-q3)*(C-q3) + 2.0*p1;
        double p  = sqrt(p2/6.0);
        double lam;
        if (p > 0.0) {
            double ip = 1.0/p;
            double b00=(A-q3)*ip, b11=(B-q3)*ip, b22=(C-q3)*ip;
            double b01=D*ip, b02=E*ip, b12=F*ip;
            double det = b00*(b11*b22 - b12*b12)
                       - b01*(b01*b22 - b12*b02)
                       + b02*(b01*b12 - b11*b02);
            double rr = det*0.5;
            rr = fmin(1.0, fmax(-1.0, rr));
            lam = q3 + 2.0*p*cos(acos(rr)/3.0);
        } else lam = q3;

        double r0x=A-lam, r0y=D,     r0z=E;
        double r1x=D,     r1y=B-lam, r1z=F;
        double r2x=E,     r2y=F,     r2z=C-lam;
        double c1x=r0y*r1z-r0z*r1y, c1y=r0z*r1x-r0x*r1z, c1z=r0x*r1y-r0y*r1x;
        double c2x=r0y*r2z-r0z*r2y, c2y=r0z*r2x-r0x*r2z, c2z=r0x*r2y-r0y*r2x;
        double c3x=r1y*r2z-r1z*r2y, c3y=r1z*r2x-r1x*r2z, c3z=r1x*r2y-r1y*r2x;
        double n1=c1x*c1x+c1y*c1y+c1z*c1z;
        double n2=c2x*c2x+c2y*c2y+c2z*c2z;
        double n3=c3x*c3x+c3y*c3y+c3z*c3z;
        double vx=c1x, vy=c1y, vz=c1z, bn=n1;
        if (n2 > bn) { vx=c2x; vy=c2y; vz=c2z; bn=n2; }
        if (n3 > bn) { vx=c3x; vy=c3y; vz=c3z; bn=n3; }
        if (bn < 1e-300) { vx=1.0; vy=0.0; vz=0.0; bn=1.0; }
        double inv = rsqrt(bn);
        vx*=inv; vy*=inv; vz*=inv;

        const float* vp = vec_pred + 3*i;
        double ax=vp[0], ay=vp[1], az=vp[2];
        double nrm = sqrt(ax*ax + ay*ay + az*az);
        if (nrm < 1e-8) nrm = 1e-8;
        double dt = ax*vx + ay*vy + az*vz;
        double ac = fabs(dt)/nrm;
        g_terms[i] = log(ac + 1e-6);
    }
}

// ---------------- final deterministic reduction ----------------
__global__ void reduce_kernel(int nA, float* __restrict__ out) {
    __shared__ double sm[32];
    int tid = threadIdx.x;
    double s = 0.0;
    for (int i = tid; i < nA; i += blockDim.x) s += g_terms[i];
    s = wsum_d(s);
    if ((tid & 31) == 0) sm[tid >> 5] = s;
    __syncthreads();
    if (tid < 32) {
        double v = (tid < (int)(blockDim.x >> 5)) ? sm[tid] : 0.0;
        v = wsum_d(v);
        if (tid == 0) out[0] = (float)(-v / (double)nA);
    }
}

// ---------------- launch ----------------
extern "C" void kernel_launch(void* const* d_in, const int* in_sizes, int n_in,
                              void* d_out, int out_size) {
    const float* vec_pred = (const float*)d_in[0];
    const float* pos      = (const float*)d_in[1];
    int N  = in_sizes[1] / 3;
    int nA = (int)ceil(0.1 * (double)N);

    int smem = FTPB * FP * (int)sizeof(float4);   // 80 KB point mirror
    cudaFuncSetAttribute(fps_kernel, cudaFuncAttributeMaxDynamicSharedMemorySize, smem);

    prep_kernel<<<(N + 255)/256, 256>>>(pos, N);
    fps_kernel<<<FCT, FTPB, smem>>>(N, nA);
    int wpb = 8;
    knn_loss_kernel<<<(nA + wpb - 1)/wpb, 32*wpb>>>(vec_pred, N, nA);
    reduce_kernel<<<1, 512>>>(nA, (float*)d_out);
}

// round 6
// speedup vs baseline: 1.8349x; 1.3890x over previous
#include <cuda_runtime.h>
#include <cstdint>
#include <math.h>

// ---------------- problem-scale device scratch (static, no allocation) ----------------
#define NMAX 40960
__device__ float4 g_p4[NMAX];      // x, y, z, |p|^2
__device__ int    g_anchors[8192];
__device__ double g_terms[8192];

#define KK 20
#define INFF __int_as_float(0x7f800000)
typedef unsigned long long ull;

// ---------------- prep: SoA float4 with precomputed |p|^2 ----------------
__global__ void prep_kernel(const float* __restrict__ pos, int N) {
    int j = blockIdx.x * blockDim.x + threadIdx.x;
    if (j < N) {
        float x = pos[3*j], y = pos[3*j+1], z = pos[3*j+2];
        float n2 = __fadd_rn(__fadd_rn(__fmul_rn(x,x), __fmul_rn(y,y)), __fmul_rn(z,z));
        g_p4[j] = make_float4(x, y, z, n2);
    }
}

// ---------------- FPS: 8-CTA cluster; tagged warp keys; mbarrier cluster exchange ----
#define FCT  8
#define FTPB 512
#define NW   (FTPB/32)    // 16 warps
#define FTOT (FCT*FTPB)   // 4096 threads
#define FP   10           // ceil(40000/4096)
#define NPAIR (FP/2)

__device__ __forceinline__ unsigned fps_mapa(unsigned addr, unsigned rank) {
    unsigned r;
    asm("mapa.shared::cluster.u32 %0, %1, %2;" : "=r"(r) : "r"(addr), "r"(rank));
    return r;
}
__device__ __forceinline__ unsigned smem_u32_(const void* p) {
    return (unsigned)__cvta_generic_to_shared(p);
}
__device__ __forceinline__ void cluster_sync_() {
    asm volatile("barrier.cluster.arrive.aligned;\n\tbarrier.cluster.wait.aligned;" ::: "memory");
}
__device__ __forceinline__ ull pack2(float lo, float hi) {
    ull v; asm("mov.b64 %0, {%1, %2};" : "=l"(v) : "r"(__float_as_uint(lo)), "r"(__float_as_uint(hi)));
    return v;
}
__device__ __forceinline__ void unpack2(ull v, float &lo, float &hi) {
    unsigned a, b; asm("mov.b64 {%0, %1}, %2;" : "=r"(a), "=r"(b) : "l"(v));
    lo = __uint_as_float(a); hi = __uint_as_float(b);
}
__device__ __forceinline__ ull add2_(ull a, ull b) {
    ull d; asm("add.rn.f32x2 %0, %1, %2;" : "=l"(d) : "l"(a), "l"(b)); return d;
}
__device__ __forceinline__ ull mul2_(ull a, ull b) {
    ull d; asm("mul.rn.f32x2 %0, %1, %2;" : "=l"(d) : "l"(a), "l"(b)); return d;
}
__device__ __forceinline__ ull fma2_(ull a, ull b, ull c) {
    ull d; asm("fma.rn.f32x2 %0, %1, %2, %3;" : "=l"(d) : "l"(a), "l"(b), "l"(c)); return d;
}

__global__ void __cluster_dims__(FCT,1,1) __launch_bounds__(FTPB,1)
fps_kernel(int N, int nA) {
    extern __shared__ float4 s_pts[];          // [FTPB*FP] point mirror for winner lookup
    __shared__ ull   s_wkey[NW];               // per-warp tagged keys: val32|enc16|tag16
    __shared__ ull   s_xkey[2][FCT];           // exchanged keys (double buffered)
    __shared__ ull   s_xy  [2][FCT];           // exchanged winner x,y
    __shared__ float s_z   [2][FCT];           // exchanged winner z
    __shared__ ull   s_bar [2];                // mbarriers (count = FCT)

    int tid  = threadIdx.x;
    unsigned rank; asm("mov.u32 %0, %%cluster_ctarank;" : "=r"(rank));
    int gt   = (int)rank * FTPB + tid;
    int lane = tid & 31, wid = tid >> 5;

    if (tid == 0) {
        asm volatile("mbarrier.init.shared.b64 [%0], %1;" :: "r"(smem_u32_(&s_bar[0])), "r"(FCT) : "memory");
        asm volatile("mbarrier.init.shared.b64 [%0], %1;" :: "r"(smem_u32_(&s_bar[1])), "r"(FCT) : "memory");
    }
    if (tid < NW) s_wkey[tid] = 0ull;          // tag 0 != round 1

    // remote addresses (warp0 lanes 0..7 target rank = lane)
    unsigned rka0=0, rka1=0, rxa0=0, rxa1=0, rza0=0, rza1=0, rba0=0, rba1=0;
    if (wid == 0 && lane < FCT) {
        rka0 = fps_mapa(smem_u32_(&s_xkey[0][rank]), (unsigned)lane);
        rka1 = fps_mapa(smem_u32_(&s_xkey[1][rank]), (unsigned)lane);
        rxa0 = fps_mapa(smem_u32_(&s_xy [0][rank]), (unsigned)lane);
        rxa1 = fps_mapa(smem_u32_(&s_xy [1][rank]), (unsigned)lane);
        rza0 = fps_mapa(smem_u32_(&s_z  [0][rank]), (unsigned)lane);
        rza1 = fps_mapa(smem_u32_(&s_z  [1][rank]), (unsigned)lane);
        rba0 = fps_mapa(smem_u32_(&s_bar[0]),       (unsigned)lane);
        rba1 = fps_mapa(smem_u32_(&s_bar[1]),       (unsigned)lane);
    }

    // register-resident points (packed pairs) + min-distance array
    ull X2[NPAIR], Y2[NPAIR], Z2[NPAIR];
    float md[FP];
    bool has10 = (9*FTOT + gt) < N;

    float4 a0 = g_p4[0];
    float bv = -1.0f; int bi = 0;
    float xs[FP], ys[FP], zs[FP];
    #pragma unroll
    for (int s = 0; s < FP; s++) {
        int gi = s*FTOT + gt;                  // < NMAX; pad reads zero-init tail
        float4 q = g_p4[gi];
        s_pts[tid*FP + s] = q;
        xs[s]=q.x; ys[s]=q.y; zs[s]=q.z;
        float dx=q.x-a0.x, dy=q.y-a0.y, dz=q.z-a0.z;
        float d = fmaf(dx,dx, fmaf(dy,dy, dz*dz));
        bool valid = (s < 9) || has10;
        md[s] = valid ? d : -1.0f;
        if (valid && d > bv) { bv = d; bi = gi; }
    }
    #pragma unroll
    for (int p = 0; p < NPAIR; p++) {
        X2[p] = pack2(xs[2*p], xs[2*p+1]);
        Y2[p] = pack2(ys[2*p], ys[2*p+1]);
        Z2[p] = pack2(zs[2*p], zs[2*p+1]);
    }
    if (rank == 0 && tid == 0) g_anchors[0] = 0;
    __syncthreads();      // s_pts, s_wkey, bars ready (CTA-local)
    cluster_sync_();      // visible cluster-wide before any remote store

    unsigned wkbase = smem_u32_(&s_wkey[0]);
    int ph0 = 0, ph1 = 0;

    for (int it = 1; it < nA; ++it) {
        int buf = it & 1;
        ull tag = (ull)((unsigned)it & 0xFFFFu);

        // ---- warp argmax: (max value, min index on tie) ----
        unsigned vb   = __float_as_uint(bv);                  // bv >= 0 -> monotone bits
        unsigned wmax = __reduce_max_sync(0xFFFFFFFFu, vb);
        unsigned cand = (vb == wmax) ? (unsigned)bi : 0xFFFFFFFFu;
        unsigned widx = __reduce_min_sync(0xFFFFFFFFu, cand); // warp winner global idx

        // lane0 posts tagged warp key (single u64 word -> no bar.sync needed)
        if (lane == 0) {
            ull wkey = ((ull)wmax << 32) | ((ull)(0xFFFFu - widx) << 16) | tag;
            asm volatile("st.volatile.shared.u64 [%0], %1;" :: "r"(wkbase + (unsigned)(wid*8)), "l"(wkey) : "memory");
        }

        // ---- warp0 only: poll 16 tagged slots (1 per lane), block REDUX, ship ----
        if (wid == 0) {
            ull k = 0ull;
            if (lane < NW) {
                unsigned a = wkbase + (unsigned)(lane*8);
                do {
                    asm volatile("ld.volatile.shared.u64 %0, [%1];" : "=l"(k) : "r"(a));
                } while ((unsigned)(k & 0xFFFFull) != (unsigned)tag);
            }
            unsigned kv   = (unsigned)(k >> 32);
            unsigned bmax = __reduce_max_sync(0xFFFFFFFFu, kv);
            unsigned cenc = (kv == bmax && lane < NW) ? (unsigned)((k >> 16) & 0xFFFFull) : 0u;
            unsigned benc = __reduce_max_sync(0xFFFFFFFFu, cenc);   // max enc == min idx
            // block winner is in this CTA: get its position from the mirror
            unsigned bidx = 0xFFFFu - benc;
            int tloc = (int)(bidx & (FTOT-1)) - (int)rank * FTPB;
            int sI   = (int)(bidx >> 12);
            float4 bp = s_pts[tloc*FP + sI];
            if (lane < FCT) {
                ull blkkey = ((ull)bmax << 32) | ((ull)benc << 16) | tag;
                unsigned ka = buf ? rka1 : rka0;
                unsigned xa = buf ? rxa1 : rxa0;
                unsigned za = buf ? rza1 : rza0;
                unsigned ba = buf ? rba1 : rba0;
                ull xy = pack2(bp.x, bp.y);
                asm volatile("st.shared::cluster.u64 [%0], %1;" :: "r"(xa), "l"(xy) : "memory");
                asm volatile("st.shared::cluster.u32 [%0], %1;" :: "r"(za), "r"(__float_as_uint(bp.z)) : "memory");
                asm volatile("st.shared::cluster.u64 [%0], %1;" :: "r"(ka), "l"(blkkey) : "memory");
                asm volatile("mbarrier.arrive.release.cluster.shared::cluster.b64 _, [%0];" :: "r"(ba) : "memory");
            }
        }

        // ---- everyone: HW-sleep wait for 8 arrivals (no LSU spinning) ----
        {
            int par = buf ? ph1 : ph0;
            unsigned ba = smem_u32_(&s_bar[buf]);
            unsigned done;
            asm volatile("{\n\t.reg .pred p;\n\t"
                         "mbarrier.try_wait.parity.acquire.cluster.shared::cta.b64 p, [%1], %2;\n\t"
                         "selp.b32 %0, 1, 0, p;\n\t}"
                         : "=r"(done) : "r"(ba), "r"(par) : "memory");
            while (!done) {
                asm volatile("{\n\t.reg .pred p;\n\t"
                             "mbarrier.try_wait.parity.acquire.cluster.shared::cta.b64 p, [%1], %2, 0x989680;\n\t"
                             "selp.b32 %0, 1, 0, p;\n\t}"
                             : "=r"(done) : "r"(ba), "r"(par) : "memory");
            }
            if (buf) ph1 ^= 1; else ph0 ^= 1;
        }

        // ---- consume: max over 8 unique keys, read winner position locally ----
        ull k0=s_xkey[buf][0], k1=s_xkey[buf][1], k2=s_xkey[buf][2], k3=s_xkey[buf][3];
        ull k4=s_xkey[buf][4], k5=s_xkey[buf][5], k6=s_xkey[buf][6], k7=s_xkey[buf][7];
        ull ka_ = k0; int ra = 0; if (k1 > ka_) { ka_ = k1; ra = 1; }
        ull kb_ = k2; int rb = 2; if (k3 > kb_) { kb_ = k3; rb = 3; }
        ull kc_ = k4; int rc = 4; if (k5 > kc_) { kc_ = k5; rc = 5; }
        ull kd_ = k6; int rd = 6; if (k7 > kd_) { kd_ = k7; rd = 7; }
        if (kb_ > ka_) { ka_ = kb_; ra = rb; }
        if (kd_ > kc_) { kc_ = kd_; rc = rd; }
        if (kc_ > ka_) { ka_ = kc_; ra = rc; }
        float apx, apy, apz;
        unpack2(s_xy[buf][ra], apx, apy);
        apz = s_z[buf][ra];
        if (rank == 0 && tid == 0)
            g_anchors[it] = (int)(0xFFFFu - (unsigned)((ka_ >> 16) & 0xFFFFull));

        // ---- update min-distances (f32x2 packed) + local argmax ----
        ull nax = pack2(-apx, -apx), nay = pack2(-apy, -apy), naz = pack2(-apz, -apz);
        #pragma unroll
        for (int p = 0; p < NPAIR; p++) {
            ull dx2 = add2_(X2[p], nax);
            ull dy2 = add2_(Y2[p], nay);
            ull dz2 = add2_(Z2[p], naz);
            ull dd  = fma2_(dx2, dx2, fma2_(dy2, dy2, mul2_(dz2, dz2)));
            float dlo, dhi; unpack2(dd, dlo, dhi);
            md[2*p]   = fminf(md[2*p],   dlo);
            md[2*p+1] = fminf(md[2*p+1], dhi);
        }
        bv = md[0]; bi = gt;
        #pragma unroll
        for (int s = 1; s < 9; s++) {
            if (md[s] > bv) { bv = md[s]; bi = gt + s*FTOT; }
        }
        if (has10 && md[9] > bv) { bv = md[9]; bi = gt + 9*FTOT; }
    }
    cluster_sync_();
}

// ---------------- KNN + PCA + per-anchor loss term: one warp per anchor ----------------
__device__ __forceinline__ double wsum_d(double v) {
    #pragma unroll
    for (int o = 16; o > 0; o >>= 1) v += __shfl_xor_sync(0xFFFFFFFFu, v, o);
    return v;
}

__global__ void knn_loss_kernel(const float* __restrict__ vec_pred, int N, int nA) {
    int wid  = threadIdx.x >> 5;
    int lane = threadIdx.x & 31;
    int i = blockIdx.x * (blockDim.x >> 5) + wid;
    if (i >= nA) return;

    int a = g_anchors[i];
    float4 ap = g_p4[a];
    float na2 = ap.w;

    float vv[KK]; int ii[KK];
    #pragma unroll
    for (int k = 0; k < KK; k++) { vv[k] = INFF; ii[k] = 0x7fffffff; }

    int steps = N >> 5;
    #pragma unroll 4
    for (int s = 0; s < steps; s++) {
        int j = (s << 5) + lane;
        float4 q = g_p4[j];
        float dot = fmaf(ap.z, q.z, fmaf(ap.y, q.y, ap.x*q.x));
        float d2 = (na2 - 2.0f*dot) + q.w;               // reference's expansion
        if (d2 < vv[KK-1]) {
            float cd = d2; int cj = j;
            #pragma unroll
            for (int k = 0; k < KK; k++) {
                if (cd < vv[k]) { float tv=vv[k]; int ti=ii[k]; vv[k]=cd; ii[k]=cj; cd=tv; cj=ti; }
            }
        }
    }
    int rem = N - (steps << 5);
    if (rem > 0 && lane < rem) {
        int j = (steps << 5) + lane;
        float4 q = g_p4[j];
        float dot = fmaf(ap.z, q.z, fmaf(ap.y, q.y, ap.x*q.x));
        float d2 = (na2 - 2.0f*dot) + q.w;
        if (d2 < vv[KK-1]) {
            float cd = d2; int cj = j;
            #pragma unroll
            for (int k = 0; k < KK; k++) {
                if (cd < vv[k]) { float tv=vv[k]; int ti=ii[k]; vv[k]=cd; ii[k]=cj; cd=tv; cj=ti; }
            }
        }
    }

    // 20-round warp merge; ties -> lower index (matches jax top_k)
    int nbr = -1;
    for (int r = 0; r < KK; r++) {
        unsigned m = __float_as_uint(vv[0]);
        m = (m & 0x80000000u) ? ~m : (m | 0x80000000u);
        ull key = ((ull)m << 32) | (unsigned)ii[0];
        #pragma unroll
        for (int o = 16; o > 0; o >>= 1) {
            ull k2 = __shfl_xor_sync(0xFFFFFFFFu, key, o);
            if (k2 < key) key = k2;
        }
        int widx = (int)(unsigned)key;
        if (lane == r) nbr = widx;
        if (ii[0] == widx) {
            #pragma unroll
            for (int k = 0; k < KK-1; k++) { vv[k]=vv[k+1]; ii[k]=ii[k+1]; }
            vv[KK-1] = INFF; ii[KK-1] = 0x7fffffff;
        }
    }

    // gather neighbors (lanes 0..19), covariance in double
    double x=0.0, y=0.0, z=0.0;
    if (lane < KK) { float4 q = g_p4[nbr]; x=q.x; y=q.y; z=q.z; }
    double sx = wsum_d(x), sy = wsum_d(y), sz = wsum_d(z);
    double mx = sx/KK, my = sy/KK, mz = sz/KK;
    double cx = (lane<KK) ? x-mx : 0.0;
    double cy = (lane<KK) ? y-my : 0.0;
    double cz = (lane<KK) ? z-mz : 0.0;
    double xx = wsum_d(cx*cx), xy = wsum_d(cx*cy), xz = wsum_d(cx*cz);
    double yy = wsum_d(cy*cy), yz = wsum_d(cy*cz), zz = wsum_d(cz*cz);

    if (lane == 0) {
        double A=xx, B=yy, C=zz, D=xy, E=xz, F=yz;
        double p1 = D*D + E*E + F*F;
        double q3 = (A+B+C)/3.0;
        double p2 = (A-q3)*(A-q3) + (B-q3)*(B-q3) + (C-q3)*(C-q3) + 2.0*p1;
        double p  = sqrt(p2/6.0);
        double lam;
        if (p > 0.0) {
            double ip = 1.0/p;
            double b00=(A-q3)*ip, b11=(B-q3)*ip, b22=(C-q3)*ip;
            double b01=D*ip, b02=E*ip, b12=F*ip;
            double det = b00*(b11*b22 - b12*b12)
                       - b01*(b01*b22 - b12*b02)
                       + b02*(b01*b12 - b11*b02);
            double rr = det*0.5;
            rr = fmin(1.0, fmax(-1.0, rr));
            lam = q3 + 2.0*p*cos(acos(rr)/3.0);
        } else lam = q3;

        double r0x=A-lam, r0y=D,     r0z=E;
        double r1x=D,     r1y=B-lam, r1z=F;
        double r2x=E,     r2y=F,     r2z=C-lam;
        double c1x=r0y*r1z-r0z*r1y, c1y=r0z*r1x-r0x*r1z, c1z=r0x*r1y-r0y*r1x;
        double c2x=r0y*r2z-r0z*r2y, c2y=r0z*r2x-r0x*r2z, c2z=r0x*r2y-r0y*r2x;
        double c3x=r1y*r2z-r1z*r2y, c3y=r1z*r2x-r1x*r2z, c3z=r1x*r2y-r1y*r2x;
        double n1=c1x*c1x+c1y*c1y+c1z*c1z;
        double n2=c2x*c2x+c2y*c2y+c2z*c2z;
        double n3=c3x*c3x+c3y*c3y+c3z*c3z;
        double vx=c1x, vy=c1y, vz=c1z, bn=n1;
        if (n2 > bn) { vx=c2x; vy=c2y; vz=c2z; bn=n2; }
        if (n3 > bn) { vx=c3x; vy=c3y; vz=c3z; bn=n3; }
        if (bn < 1e-300) { vx=1.0; vy=0.0; vz=0.0; bn=1.0; }
        double inv = rsqrt(bn);
        vx*=inv; vy*=inv; vz*=inv;

        const float* vp = vec_pred + 3*i;
        double ax=vp[0], ay=vp[1], az=vp[2];
        double nrm = sqrt(ax*ax + ay*ay + az*az);
        if (nrm < 1e-8) nrm = 1e-8;
        double dt = ax*vx + ay*vy + az*vz;
        double ac = fabs(dt)/nrm;
        g_terms[i] = log(ac + 1e-6);
    }
}

// ---------------- final deterministic reduction ----------------
__global__ void reduce_kernel(int nA, float* __restrict__ out) {
    __shared__ double sm[32];
    int tid = threadIdx.x;
    double s = 0.0;
    for (int i = tid; i < nA; i += blockDim.x) s += g_terms[i];
    s = wsum_d(s);
    if ((tid & 31) == 0) sm[tid >> 5] = s;
    __syncthreads();
    if (tid < 32) {
        double v = (tid < (int)(blockDim.x >> 5)) ? sm[tid] : 0.0;
        v = wsum_d(v);
        if (tid == 0) out[0] = (float)(-v / (double)nA);
    }
}

// ---------------- launch ----------------
extern "C" void kernel_launch(void* const* d_in, const int* in_sizes, int n_in,
                              void* d_out, int out_size) {
    const float* vec_pred = (const float*)d_in[0];
    const float* pos      = (const float*)d_in[1];
    int N  = in_sizes[1] / 3;
    int nA = (int)ceil(0.1 * (double)N);

    int smem = FTPB * FP * (int)sizeof(float4);   // 80 KB point mirror
    cudaFuncSetAttribute(fps_kernel, cudaFuncAttributeMaxDynamicSharedMemorySize, smem);

    prep_kernel<<<(N + 255)/256, 256>>>(pos, N);
    fps_kernel<<<FCT, FTPB, smem>>>(N, nA);
    int wpb = 8;
    knn_loss_kernel<<<(nA + wpb - 1)/wpb, 32*wpb>>>(vec_pred, N, nA);
    reduce_kernel<<<1, 512>>>(nA, (float*)d_out);
}